// round 6
// baseline (speedup 1.0000x reference)
#include <cuda_runtime.h>
#include <cuda_bf16.h>

// HMM forward, time-parallel 3-phase decomposition (R5: occupancy + pipelining).
//   pass1 : per (seq,chunk k=1..14) 4x4 chunk transfer matrix, 4 blocks/SM
//   mid   : per seq, scalar chunk0 + 14 matvecs -> exact chunk-start log-alphas
//   pass2 : per (seq,chunk) recompute 32 alphas; 3 blocks/SM via 2-state
//           staging rounds; y/mask prefetch + batched emission gathers.

#define TT   512
#define NSEQ 16384
#define KM   14
#define MAXV 8192
#define LN2f 0.69314718055994530942f
#define L2Ef 1.44269504088896340736f

__device__ uint2  g_BtH[MAXV];          // bf16x4 linear emissions per token
__device__ float4 g_M [KM * 4 * NSEQ];  // chunk matrices [k-1][row][seq]
__device__ float  g_Mc[KM * NSEQ];      // chunk matrix log offsets
__device__ float4 g_S [16 * NSEQ];      // log-alpha at t=32k-1, k=1..15

struct W8 { float AEB, ASB, ABM, AMM, ABE, AME, AES, ASS; };

// A[p][s] = logA[p*4+s]; allowed preds: in(B)={E,S}, in(M)=in(E)={B,M}, in(S)={E,S}
__device__ __forceinline__ W8 load_w(const float* __restrict__ logA) {
    W8 w;
    w.AEB = expf(__ldg(&logA[8]));
    w.ASB = expf(__ldg(&logA[12]));
    w.ABM = expf(__ldg(&logA[1]));
    w.AMM = expf(__ldg(&logA[5]));
    w.ABE = expf(__ldg(&logA[2]));
    w.AME = expf(__ldg(&logA[6]));
    w.AES = expf(__ldg(&logA[11]));
    w.ASS = expf(__ldg(&logA[15]));
    return w;
}

__device__ __forceinline__ void unp(uint2 v, float& e0, float& e1, float& e2, float& e3) {
    e0 = __uint_as_float(v.x << 16);
    e1 = __uint_as_float(v.x & 0xFFFF0000u);
    e2 = __uint_as_float(v.y << 16);
    e3 = __uint_as_float(v.y & 0xFFFF0000u);
}

__device__ __forceinline__ float getc(float4 a, int s) {
    return s == 0 ? a.x : s == 1 ? a.y : s == 2 ? a.z : a.w;
}

// ---------------- prep: bf16x4 emission table ----------------
__global__ void prep_kernel(const float* __restrict__ logB, int NV) {
    int i = blockIdx.x * blockDim.x + threadIdx.x;
    if (i >= NV) return;
    unsigned b0 = (unsigned)__bfloat16_as_ushort(__float2bfloat16(expf(logB[i])));
    unsigned b1 = (unsigned)__bfloat16_as_ushort(__float2bfloat16(expf(logB[NV + i])));
    unsigned b2 = (unsigned)__bfloat16_as_ushort(__float2bfloat16(expf(logB[2 * NV + i])));
    unsigned b3 = (unsigned)__bfloat16_as_ushort(__float2bfloat16(expf(logB[3 * NV + i])));
    uint2 v; v.x = b0 | (b1 << 16); v.y = b2 | (b3 << 16);
    g_BtH[i] = v;
}

// ---------------- pass1: chunk transfer matrices ----------------
__global__ __launch_bounds__(256, 4) void pass1_kernel(
    const int* __restrict__ Y, const float* __restrict__ mask,
    const float* __restrict__ logA, int N, int NV)
{
    extern __shared__ uint2 s_tab1[];
    for (int i = threadIdx.x; i < NV; i += 256) s_tab1[i] = g_BtH[i];
    __syncthreads();

    int tau = blockIdx.x * 256 + threadIdx.x;
    if (tau >= KM * N) return;
    int k   = tau / N + 1;               // 1..14
    int seq = tau - (k - 1) * N;

    W8 w = load_w(logA);
    float4 M0 = {1, 0, 0, 0}, M1 = {0, 1, 0, 0}, M2 = {0, 0, 1, 0}, M3 = {0, 0, 0, 1};
    float c = 0.f;
    const int4*   yp = (const int4*)(Y    + (size_t)seq * TT + 32 * k);
    const float4* mp = (const float4*)(mask + (size_t)seq * TT + 32 * k);

#pragma unroll 1
    for (int jj = 0; jj < 8; jj++) {
        int4   y4 = __ldg(yp + jj);
        float4 m4 = __ldg(mp + jj);
        // batched gathers: issued back-to-back, overlapped
        uint2 evs[4];
        evs[0] = s_tab1[y4.x]; evs[1] = s_tab1[y4.y];
        evs[2] = s_tab1[y4.z]; evs[3] = s_tab1[y4.w];
        float ma[4] = {m4.x, m4.y, m4.z, m4.w};
#pragma unroll
        for (int q = 0; q < 4; q++) {
            if (ma[q] == 1.0f) {
                float e0, e1, e2, e3; unp(evs[q], e0, e1, e2, e3);
                float u, v;
                // rows B,S from old rows E,S (then E,S dead)
                u = e0 * w.AEB; v = e0 * w.ASB;
                float4 nB = {fmaf(v, M3.x, u * M2.x), fmaf(v, M3.y, u * M2.y),
                             fmaf(v, M3.z, u * M2.z), fmaf(v, M3.w, u * M2.w)};
                u = e3 * w.AES; v = e3 * w.ASS;
                float4 nS = {fmaf(v, M3.x, u * M2.x), fmaf(v, M3.y, u * M2.y),
                             fmaf(v, M3.z, u * M2.z), fmaf(v, M3.w, u * M2.w)};
                // rows M,E from old rows B,M
                u = e1 * w.ABM; v = e1 * w.AMM;
                float4 nM = {fmaf(v, M1.x, u * M0.x), fmaf(v, M1.y, u * M0.y),
                             fmaf(v, M1.z, u * M0.z), fmaf(v, M1.w, u * M0.w)};
                u = e2 * w.ABE; v = e2 * w.AME;
                float4 nE = {fmaf(v, M1.x, u * M0.x), fmaf(v, M1.y, u * M0.y),
                             fmaf(v, M1.z, u * M0.z), fmaf(v, M1.w, u * M0.w)};
                M0 = nB; M1 = nM; M2 = nE; M3 = nS;
            }
        }
        // rescale (exponent bits, exact)
        float mx = fmaxf(fmaxf(fmaxf(fmaxf(M0.x, M0.y), fmaxf(M0.z, M0.w)),
                               fmaxf(fmaxf(M1.x, M1.y), fmaxf(M1.z, M1.w))),
                         fmaxf(fmaxf(fmaxf(M2.x, M2.y), fmaxf(M2.z, M2.w)),
                               fmaxf(fmaxf(M3.x, M3.y), fmaxf(M3.z, M3.w))));
        int eb = __float_as_int(mx) >> 23;
        float sc = __int_as_float((254 - eb) << 23);
        c = fmaf((float)(eb - 127), LN2f, c);
        M0.x *= sc; M0.y *= sc; M0.z *= sc; M0.w *= sc;
        M1.x *= sc; M1.y *= sc; M1.z *= sc; M1.w *= sc;
        M2.x *= sc; M2.y *= sc; M2.z *= sc; M2.w *= sc;
        M3.x *= sc; M3.y *= sc; M3.z *= sc; M3.w *= sc;
    }
    int b = ((k - 1) * 4) * N + seq;
    g_M[b] = M0; g_M[b + N] = M1; g_M[b + 2 * N] = M2; g_M[b + 3 * N] = M3;
    g_Mc[(k - 1) * N + seq] = c;
}

// ---------------- middle: chunk-boundary log-alphas ----------------
__global__ __launch_bounds__(256) void mid_kernel(
    const int* __restrict__ Y, const float* __restrict__ mask,
    const float* __restrict__ logpi, const float* __restrict__ logA,
    const float* __restrict__ logB, int N, int NV)
{
    int seq = blockIdx.x * 256 + threadIdx.x;
    if (seq >= N) return;
    W8 w = load_w(logA);

    int y0 = __ldg(&Y[(size_t)seq * TT]);
    float a0 = __ldg(&logpi[0]) + __ldg(&logB[y0]);
    float a1 = __ldg(&logpi[1]) + __ldg(&logB[NV + y0]);
    float a2 = __ldg(&logpi[2]) + __ldg(&logB[2 * NV + y0]);
    float a3 = __ldg(&logpi[3]) + __ldg(&logB[3 * NV + y0]);
    float c = fmaxf(fmaxf(a0, a1), fmaxf(a2, a3));
    float p0 = exp2f((a0 - c) * L2Ef), p1 = exp2f((a1 - c) * L2Ef);
    float p2 = exp2f((a2 - c) * L2Ef), p3 = exp2f((a3 - c) * L2Ef);

    for (int t = 1; t < 32; t++) {
        int   y = __ldg(&Y[(size_t)seq * TT + t]);
        float m = __ldg(&mask[(size_t)seq * TT + t]);
        uint2 ev = __ldg(&g_BtH[y]);
        if (m == 1.0f) {
            float e0, e1, e2, e3; unp(ev, e0, e1, e2, e3);
            float qB = e0 * fmaf(w.ASB, p3, w.AEB * p2);
            float qM = e1 * fmaf(w.AMM, p1, w.ABM * p0);
            float qE = e2 * fmaf(w.AME, p1, w.ABE * p0);
            float qS = e3 * fmaf(w.ASS, p3, w.AES * p2);
            float mx = fmaxf(fmaxf(qB, qM), fmaxf(qE, qS));
            int eb = __float_as_int(mx) >> 23;
            float sc = __int_as_float((254 - eb) << 23);
            c = fmaf((float)(eb - 127), LN2f, c);
            p0 = qB * sc; p1 = qM * sc; p2 = qE * sc; p3 = qS * sc;
        }
    }
    g_S[1 * N + seq] = make_float4(fmaf(__log2f(p0), LN2f, c), fmaf(__log2f(p1), LN2f, c),
                                   fmaf(__log2f(p2), LN2f, c), fmaf(__log2f(p3), LN2f, c));
    for (int k = 1; k <= KM; k++) {
        int b = ((k - 1) * 4) * N + seq;
        float4 r0 = __ldg(&g_M[b]);
        float4 r1 = __ldg(&g_M[b + N]);
        float4 r2 = __ldg(&g_M[b + 2 * N]);
        float4 r3 = __ldg(&g_M[b + 3 * N]);
        float cm = __ldg(&g_Mc[(k - 1) * N + seq]);
        float q0 = fmaf(r0.x, p0, fmaf(r0.y, p1, fmaf(r0.z, p2, r0.w * p3)));
        float q1 = fmaf(r1.x, p0, fmaf(r1.y, p1, fmaf(r1.z, p2, r1.w * p3)));
        float q2 = fmaf(r2.x, p0, fmaf(r2.y, p1, fmaf(r2.z, p2, r2.w * p3)));
        float q3 = fmaf(r3.x, p0, fmaf(r3.y, p1, fmaf(r3.z, p2, r3.w * p3)));
        c += cm;
        float mx = fmaxf(fmaxf(q0, q1), fmaxf(q2, q3));
        int eb = __float_as_int(mx) >> 23;
        float sc = __int_as_float((254 - eb) << 23);
        c = fmaf((float)(eb - 127), LN2f, c);
        p0 = q0 * sc; p1 = q1 * sc; p2 = q2 * sc; p3 = q3 * sc;
        g_S[(k + 1) * N + seq] =
            make_float4(fmaf(__log2f(p0), LN2f, c), fmaf(__log2f(p1), LN2f, c),
                        fmaf(__log2f(p2), LN2f, c), fmaf(__log2f(p3), LN2f, c));
    }
}

// ---------------- pass2: emit all alphas ----------------
// block = 256 threads = 16 seqs x 16 chunks; 3 blocks/SM.
// smem: bf16 table (48000B) + 2-state staging buffer (2*3072 floats, stride-12).
__global__ __launch_bounds__(256, 3) void pass2_kernel(
    const int* __restrict__ Y, const float* __restrict__ mask,
    const float* __restrict__ logpi, const float* __restrict__ logA,
    const float* __restrict__ logB, float* __restrict__ out, int N, int NV)
{
    extern __shared__ char smem[];
    uint2* tab = (uint2*)smem;
    float* buf = (float*)(smem + (size_t)NV * 8);
    for (int i = threadIdx.x; i < NV; i += 256) tab[i] = g_BtH[i];
    __syncthreads();

    const int tid = threadIdx.x, lane = tid & 31, wid = tid >> 5;
    const int seq_l = tid >> 4, k = tid & 15;
    const int bseq = blockIdx.x * 16;
    const int seq = bseq + seq_l;
    W8 w = load_w(logA);

    float p0, p1, p2, p3, c, ap0, ap1, ap2, ap3;
    if (k == 0) {
        int y0 = __ldg(&Y[(size_t)seq * TT]);
        ap0 = __ldg(&logpi[0]) + __ldg(&logB[y0]);
        ap1 = __ldg(&logpi[1]) + __ldg(&logB[NV + y0]);
        ap2 = __ldg(&logpi[2]) + __ldg(&logB[2 * NV + y0]);
        ap3 = __ldg(&logpi[3]) + __ldg(&logB[3 * NV + y0]);
    } else {
        float4 a = __ldg(&g_S[k * N + seq]);
        ap0 = a.x; ap1 = a.y; ap2 = a.z; ap3 = a.w;
    }
    c  = fmaxf(fmaxf(ap0, ap1), fmaxf(ap2, ap3));
    p0 = exp2f((ap0 - c) * L2Ef); p1 = exp2f((ap1 - c) * L2Ef);
    p2 = exp2f((ap2 - c) * L2Ef); p3 = exp2f((ap3 - c) * L2Ef);

    const int4*   yp = (const int4*)(Y    + (size_t)seq * TT + 32 * k);
    const float4* mp = (const float4*)(mask + (size_t)seq * TT + 32 * k);

    // prime the half-group pipeline
    int4   y4n = __ldg(yp);
    float4 m4n = __ldg(mp);
    int li = 1;

#pragma unroll 1
    for (int g = 0; g < 4; g++) {
        float4 an[8];
#pragma unroll
        for (int h = 0; h < 2; h++) {
            int4   y4 = y4n;
            float4 m4 = m4n;
            if (li < 8) { y4n = __ldg(yp + li); m4n = __ldg(mp + li); li++; }
            // batched emission gathers for this half
            uint2 evs[4];
            evs[0] = tab[y4.x]; evs[1] = tab[y4.y];
            evs[2] = tab[y4.z]; evs[3] = tab[y4.w];
            float ma[4] = {m4.x, m4.y, m4.z, m4.w};
#pragma unroll
            for (int q = 0; q < 4; q++) {
                int j = h * 4 + q;
                if (k == 0 && g == 0 && j == 0) {
                    an[0] = make_float4(ap0, ap1, ap2, ap3);  // t=0: exact logs
                } else {
                    float e0, e1, e2, e3; unp(evs[q], e0, e1, e2, e3);
                    float qB = e0 * fmaf(w.ASB, p3, w.AEB * p2);
                    float qM = e1 * fmaf(w.AMM, p1, w.ABM * p0);
                    float qE = e2 * fmaf(w.AME, p1, w.ABE * p0);
                    float qS = e3 * fmaf(w.ASS, p3, w.AES * p2);
                    float n0 = fmaf(__log2f(qB), LN2f, c);
                    float n1 = fmaf(__log2f(qM), LN2f, c);
                    float n2 = fmaf(__log2f(qE), LN2f, c);
                    float n3 = fmaf(__log2f(qS), LN2f, c);
                    if (ma[q] == 1.0f) {
                        p0 = qB; p1 = qM; p2 = qE; p3 = qS;
                        if (q == 3) {
                            float mx = fmaxf(fmaxf(p0, p1), fmaxf(p2, p3));
                            int eb = __float_as_int(mx) >> 23;
                            float sc = __int_as_float((254 - eb) << 23);
                            c = fmaf((float)(eb - 127), LN2f, c);
                            p0 *= sc; p1 *= sc; p2 *= sc; p3 *= sc;
                        }
                    } else {
                        // log-domain blend (exact for any m); rebuild (p,c)
                        n0 = fmaf(ma[q], n0 - ap0, ap0);
                        n1 = fmaf(ma[q], n1 - ap1, ap1);
                        n2 = fmaf(ma[q], n2 - ap2, ap2);
                        n3 = fmaf(ma[q], n3 - ap3, ap3);
                        c  = fmaxf(fmaxf(n0, n1), fmaxf(n2, n3));
                        p0 = exp2f((n0 - c) * L2Ef); p1 = exp2f((n1 - c) * L2Ef);
                        p2 = exp2f((n2 - c) * L2Ef); p3 = exp2f((n3 - c) * L2Ef);
                    }
                    ap0 = n0; ap1 = n1; ap2 = n2; ap3 = n3;
                    an[j] = make_float4(n0, n1, n2, n3);
                }
            }
        }
        // two staging rounds of 2 states each (buffer 2*3072 floats)
#pragma unroll 1
        for (int rs = 0; rs < 4; rs += 2) {
#pragma unroll
            for (int sl2 = 0; sl2 < 2; sl2++) {
                int s = rs + sl2;
                float4 v0 = make_float4(getc(an[0], s), getc(an[1], s),
                                        getc(an[2], s), getc(an[3], s));
                float4 v1 = make_float4(getc(an[4], s), getc(an[5], s),
                                        getc(an[6], s), getc(an[7], s));
                *(float4*)&buf[sl2 * 3072 + tid * 12]     = v0;
                *(float4*)&buf[sl2 * 3072 + tid * 12 + 4] = v1;
            }
            __syncthreads();
            // writeout: 32 (state,seq) rows x 128 floats, coalesced STG
            for (int rg = wid; rg < 32; rg += 8) {
                int sloc = rg >> 4, sl = rg & 15;
                float* dst = out + ((size_t)(bseq + sl) * 4 + rs + sloc) * TT + g * 8;
                int srcB = sloc * 3072 + sl * 16 * 12;
#pragma unroll
                for (int it = 0; it < 4; it++) {
                    int idx = it * 32 + lane;
                    int kk = idx >> 3, j = idx & 7;
                    dst[kk * 32 + j] = buf[srcB + kk * 12 + j];
                }
            }
            __syncthreads();
        }
    }
}

extern "C" void kernel_launch(void* const* d_in, const int* in_sizes, int n_in,
                              void* d_out, int out_size) {
    const int*   Y     = (const int*)  d_in[0];
    const float* mask  = (const float*)d_in[1];
    const float* logpi = (const float*)d_in[2];
    const float* logA  = (const float*)d_in[3];
    const float* logB  = (const float*)d_in[4];
    float*       out   = (float*)d_out;

    const int N  = in_sizes[0] / TT;
    const int NV = in_sizes[4] / 4;

    const int smem1 = NV * 8;                    // 48000 B
    const int smem2 = NV * 8 + 2 * 3072 * 4;     // 72576 B

    cudaFuncSetAttribute(pass1_kernel, cudaFuncAttributeMaxDynamicSharedMemorySize, smem1);
    cudaFuncSetAttribute(pass2_kernel, cudaFuncAttributeMaxDynamicSharedMemorySize, smem2);

    prep_kernel<<<(NV + 255) / 256, 256>>>(logB, NV);
    pass1_kernel<<<(KM * N + 255) / 256, 256, smem1>>>(Y, mask, logA, N, NV);
    mid_kernel<<<(N + 255) / 256, 256>>>(Y, mask, logpi, logA, logB, N, NV);
    pass2_kernel<<<N / 16, 256, smem2>>>(Y, mask, logpi, logA, logB, out, N, NV);
}

// round 7
// speedup vs baseline: 1.0577x; 1.0577x over previous
#include <cuda_runtime.h>
#include <cuda_bf16.h>

// HMM forward, time-parallel 3-phase decomposition (R6).
//   pass1 : k=0 blocks -> chunk-0 alphas; k=1..14 blocks -> 4x4 chunk transfer
//           matrices via packed f32x2 FMA. 4 blocks/SM.
//   mid   : 14 sequential 4x4 matvecs (double-buffered row prefetch).
//   pass2 : per (seq,chunk) recompute 32 alphas; DIRECT 32B-sector stores,
//           no staging smem, no block barriers after table load.

#define TT   512
#define NSEQ 16384
#define KM   14
#define MAXV 8192
#define LN2f 0.69314718055994530942f
#define L2Ef 1.44269504088896340736f

typedef unsigned long long ull;

__device__ uint2  g_BtH[MAXV];          // bf16x4 linear emissions per token
__device__ float4 g_M [KM * 4 * NSEQ];  // chunk matrices [k-1][row][seq]
__device__ float  g_Mc[KM * NSEQ];      // chunk matrix log offsets
__device__ float4 g_S [16 * NSEQ];      // log-alpha at t=32k-1, k=1..15

struct W8 { float AEB, ASB, ABM, AMM, ABE, AME, AES, ASS; };

// A[p][s] = logA[p*4+s]; allowed preds: in(B)={E,S}, in(M)=in(E)={B,M}, in(S)={E,S}
__device__ __forceinline__ W8 load_w(const float* __restrict__ logA) {
    W8 w;
    w.AEB = expf(__ldg(&logA[8]));
    w.ASB = expf(__ldg(&logA[12]));
    w.ABM = expf(__ldg(&logA[1]));
    w.AMM = expf(__ldg(&logA[5]));
    w.ABE = expf(__ldg(&logA[2]));
    w.AME = expf(__ldg(&logA[6]));
    w.AES = expf(__ldg(&logA[11]));
    w.ASS = expf(__ldg(&logA[15]));
    return w;
}

__device__ __forceinline__ void unp(uint2 v, float& e0, float& e1, float& e2, float& e3) {
    e0 = __uint_as_float(v.x << 16);
    e1 = __uint_as_float(v.x & 0xFFFF0000u);
    e2 = __uint_as_float(v.y << 16);
    e3 = __uint_as_float(v.y & 0xFFFF0000u);
}

// ---- packed f32x2 helpers ----
__device__ __forceinline__ ull pk(float a, float b) {
    ull r; asm("mov.b64 %0, {%1, %2};" : "=l"(r) : "f"(a), "f"(b)); return r;
}
__device__ __forceinline__ ull pk2(float a) { return pk(a, a); }
__device__ __forceinline__ void upk(ull v, float& a, float& b) {
    asm("mov.b64 {%0, %1}, %2;" : "=f"(a), "=f"(b) : "l"(v));
}
__device__ __forceinline__ ull mul2(ull a, ull b) {
    ull r; asm("mul.rn.f32x2 %0, %1, %2;" : "=l"(r) : "l"(a), "l"(b)); return r;
}
__device__ __forceinline__ ull fma2(ull a, ull b, ull c) {
    ull r; asm("fma.rn.f32x2 %0, %1, %2, %3;" : "=l"(r) : "l"(a), "l"(b), "l"(c)); return r;
}

// ---------------- prep: bf16x4 emission table ----------------
__global__ void prep_kernel(const float* __restrict__ logB, int NV) {
    int i = blockIdx.x * blockDim.x + threadIdx.x;
    if (i >= NV) return;
    unsigned b0 = (unsigned)__bfloat16_as_ushort(__float2bfloat16(expf(logB[i])));
    unsigned b1 = (unsigned)__bfloat16_as_ushort(__float2bfloat16(expf(logB[NV + i])));
    unsigned b2 = (unsigned)__bfloat16_as_ushort(__float2bfloat16(expf(logB[2 * NV + i])));
    unsigned b3 = (unsigned)__bfloat16_as_ushort(__float2bfloat16(expf(logB[3 * NV + i])));
    uint2 v; v.x = b0 | (b1 << 16); v.y = b2 | (b3 << 16);
    g_BtH[i] = v;
}

// ---------------- pass1: chunk0 alphas (k=0) + transfer matrices (k=1..14) ----
__global__ __launch_bounds__(256, 4) void pass1_kernel(
    const int* __restrict__ Y, const float* __restrict__ mask,
    const float* __restrict__ logpi, const float* __restrict__ logA,
    const float* __restrict__ logB, int N, int NV)
{
    extern __shared__ uint2 s_tab1[];
    for (int i = threadIdx.x; i < NV; i += 256) s_tab1[i] = g_BtH[i];
    __syncthreads();

    int tau = blockIdx.x * 256 + threadIdx.x;
    if (tau >= (KM + 1) * N) return;
    int k   = tau / N;                  // uniform per block (N % 256 == 0)
    int seq = tau - k * N;

    W8 w = load_w(logA);

    if (k == 0) {
        // ---- chunk-0 alpha recurrence (31 steps), write g_S[1] ----
        int y0 = __ldg(&Y[(size_t)seq * TT]);
        float a0 = __ldg(&logpi[0]) + __ldg(&logB[y0]);
        float a1 = __ldg(&logpi[1]) + __ldg(&logB[NV + y0]);
        float a2 = __ldg(&logpi[2]) + __ldg(&logB[2 * NV + y0]);
        float a3 = __ldg(&logpi[3]) + __ldg(&logB[3 * NV + y0]);
        float c = fmaxf(fmaxf(a0, a1), fmaxf(a2, a3));
        float p0 = exp2f((a0 - c) * L2Ef), p1 = exp2f((a1 - c) * L2Ef);
        float p2 = exp2f((a2 - c) * L2Ef), p3 = exp2f((a3 - c) * L2Ef);

        const int4*   yp = (const int4*)(Y    + (size_t)seq * TT);
        const float4* mp = (const float4*)(mask + (size_t)seq * TT);
#pragma unroll 1
        for (int jj = 0; jj < 8; jj++) {
            int4   y4 = __ldg(yp + jj);
            float4 m4 = __ldg(mp + jj);
            uint2 evs[4];
            evs[0] = s_tab1[y4.x]; evs[1] = s_tab1[y4.y];
            evs[2] = s_tab1[y4.z]; evs[3] = s_tab1[y4.w];
            float ma[4] = {m4.x, m4.y, m4.z, m4.w};
#pragma unroll
            for (int q = 0; q < 4; q++) {
                if (jj == 0 && q == 0) continue;         // t = 0 done above
                if (ma[q] == 1.0f) {
                    float e0, e1, e2, e3; unp(evs[q], e0, e1, e2, e3);
                    float qB = e0 * fmaf(w.ASB, p3, w.AEB * p2);
                    float qM = e1 * fmaf(w.AMM, p1, w.ABM * p0);
                    float qE = e2 * fmaf(w.AME, p1, w.ABE * p0);
                    float qS = e3 * fmaf(w.ASS, p3, w.AES * p2);
                    p0 = qB; p1 = qM; p2 = qE; p3 = qS;
                }
                if (q == 3) {
                    float mx = fmaxf(fmaxf(p0, p1), fmaxf(p2, p3));
                    int eb = __float_as_int(mx) >> 23;
                    float sc = __int_as_float((254 - eb) << 23);
                    c = fmaf((float)(eb - 127), LN2f, c);
                    p0 *= sc; p1 *= sc; p2 *= sc; p3 *= sc;
                }
            }
        }
        g_S[N + seq] = make_float4(fmaf(__log2f(p0), LN2f, c), fmaf(__log2f(p1), LN2f, c),
                                   fmaf(__log2f(p2), LN2f, c), fmaf(__log2f(p3), LN2f, c));
        return;
    }

    // ---- transfer matrix for chunk k (f32x2 packed rows) ----
    ull R0a = pk(1.f, 0.f), R0b = pk(0.f, 0.f);   // row B
    ull R1a = pk(0.f, 1.f), R1b = pk(0.f, 0.f);   // row M
    ull R2a = pk(0.f, 0.f), R2b = pk(1.f, 0.f);   // row E
    ull R3a = pk(0.f, 0.f), R3b = pk(0.f, 1.f);   // row S
    float c = 0.f;
    const int4*   yp = (const int4*)(Y    + (size_t)seq * TT + 32 * k);
    const float4* mp = (const float4*)(mask + (size_t)seq * TT + 32 * k);

#pragma unroll 1
    for (int jj = 0; jj < 8; jj++) {
        int4   y4 = __ldg(yp + jj);
        float4 m4 = __ldg(mp + jj);
        uint2 evs[4];
        evs[0] = s_tab1[y4.x]; evs[1] = s_tab1[y4.y];
        evs[2] = s_tab1[y4.z]; evs[3] = s_tab1[y4.w];
        float ma[4] = {m4.x, m4.y, m4.z, m4.w};
#pragma unroll
        for (int q = 0; q < 4; q++) {
            if (ma[q] == 1.0f) {
                float e0, e1, e2, e3; unp(evs[q], e0, e1, e2, e3);
                ull U0 = pk2(e0 * w.AEB), V0 = pk2(e0 * w.ASB);
                ull U1 = pk2(e1 * w.ABM), V1 = pk2(e1 * w.AMM);
                ull U2 = pk2(e2 * w.ABE), V2 = pk2(e2 * w.AME);
                ull U3 = pk2(e3 * w.AES), V3 = pk2(e3 * w.ASS);
                // rows B,S from old E,S; rows M,E from old B,M
                ull nBa = fma2(V0, R3a, mul2(U0, R2a));
                ull nBb = fma2(V0, R3b, mul2(U0, R2b));
                ull nSa = fma2(V3, R3a, mul2(U3, R2a));
                ull nSb = fma2(V3, R3b, mul2(U3, R2b));
                ull nMa = fma2(V1, R1a, mul2(U1, R0a));
                ull nMb = fma2(V1, R1b, mul2(U1, R0b));
                ull nEa = fma2(V2, R1a, mul2(U2, R0a));
                ull nEb = fma2(V2, R1b, mul2(U2, R0b));
                R0a = nBa; R0b = nBb; R1a = nMa; R1b = nMb;
                R2a = nEa; R2b = nEb; R3a = nSa; R3b = nSb;
            }
        }
        // rescale every 4 steps (exponent bits, exact)
        float f0, f1, f2, f3, f4, f5, f6, f7, g0, g1, g2, g3, g4, g5, g6, g7;
        upk(R0a, f0, f1); upk(R0b, f2, f3); upk(R1a, f4, f5); upk(R1b, f6, f7);
        upk(R2a, g0, g1); upk(R2b, g2, g3); upk(R3a, g4, g5); upk(R3b, g6, g7);
        float mx = fmaxf(fmaxf(fmaxf(fmaxf(f0, f1), fmaxf(f2, f3)),
                               fmaxf(fmaxf(f4, f5), fmaxf(f6, f7))),
                         fmaxf(fmaxf(fmaxf(g0, g1), fmaxf(g2, g3)),
                               fmaxf(fmaxf(g4, g5), fmaxf(g6, g7))));
        int eb = __float_as_int(mx) >> 23;
        float sc = __int_as_float((254 - eb) << 23);
        c = fmaf((float)(eb - 127), LN2f, c);
        ull SC = pk2(sc);
        R0a = mul2(R0a, SC); R0b = mul2(R0b, SC);
        R1a = mul2(R1a, SC); R1b = mul2(R1b, SC);
        R2a = mul2(R2a, SC); R2b = mul2(R2b, SC);
        R3a = mul2(R3a, SC); R3b = mul2(R3b, SC);
    }
    float f0, f1, f2, f3;
    int b = ((k - 1) * 4) * N + seq;
    upk(R0a, f0, f1); upk(R0b, f2, f3); g_M[b]         = make_float4(f0, f1, f2, f3);
    upk(R1a, f0, f1); upk(R1b, f2, f3); g_M[b + N]     = make_float4(f0, f1, f2, f3);
    upk(R2a, f0, f1); upk(R2b, f2, f3); g_M[b + 2 * N] = make_float4(f0, f1, f2, f3);
    upk(R3a, f0, f1); upk(R3b, f2, f3); g_M[b + 3 * N] = make_float4(f0, f1, f2, f3);
    g_Mc[(k - 1) * N + seq] = c;
}

// ---------------- middle: compose 14 matvecs, double-buffered prefetch ------
__global__ __launch_bounds__(128) void mid_kernel(int N)
{
    int seq = blockIdx.x * 128 + threadIdx.x;
    if (seq >= N) return;

    float4 a = __ldg(&g_S[N + seq]);
    float c = fmaxf(fmaxf(a.x, a.y), fmaxf(a.z, a.w));
    float p0 = exp2f((a.x - c) * L2Ef), p1 = exp2f((a.y - c) * L2Ef);
    float p2 = exp2f((a.z - c) * L2Ef), p3 = exp2f((a.w - c) * L2Ef);

    float4 r0 = __ldg(&g_M[seq]);
    float4 r1 = __ldg(&g_M[N + seq]);
    float4 r2 = __ldg(&g_M[2 * N + seq]);
    float4 r3 = __ldg(&g_M[3 * N + seq]);
    float  cm = __ldg(&g_Mc[seq]);

#pragma unroll 1
    for (int k = 1; k <= KM; k++) {
        float4 s0, s1, s2, s3; float scn = 0.f;
        if (k < KM) {
            int bn = (k * 4) * N + seq;
            s0 = __ldg(&g_M[bn]); s1 = __ldg(&g_M[bn + N]);
            s2 = __ldg(&g_M[bn + 2 * N]); s3 = __ldg(&g_M[bn + 3 * N]);
            scn = __ldg(&g_Mc[k * N + seq]);
        }
        float q0 = fmaf(r0.x, p0, fmaf(r0.y, p1, fmaf(r0.z, p2, r0.w * p3)));
        float q1 = fmaf(r1.x, p0, fmaf(r1.y, p1, fmaf(r1.z, p2, r1.w * p3)));
        float q2 = fmaf(r2.x, p0, fmaf(r2.y, p1, fmaf(r2.z, p2, r2.w * p3)));
        float q3 = fmaf(r3.x, p0, fmaf(r3.y, p1, fmaf(r3.z, p2, r3.w * p3)));
        c += cm;
        float mx = fmaxf(fmaxf(q0, q1), fmaxf(q2, q3));
        int eb = __float_as_int(mx) >> 23;
        float sc = __int_as_float((254 - eb) << 23);
        c = fmaf((float)(eb - 127), LN2f, c);
        p0 = q0 * sc; p1 = q1 * sc; p2 = q2 * sc; p3 = q3 * sc;
        g_S[(k + 1) * N + seq] =
            make_float4(fmaf(__log2f(p0), LN2f, c), fmaf(__log2f(p1), LN2f, c),
                        fmaf(__log2f(p2), LN2f, c), fmaf(__log2f(p3), LN2f, c));
        r0 = s0; r1 = s1; r2 = s2; r3 = s3; cm = scn;
    }
}

// ---------------- pass2: emit all alphas, direct 32B-sector stores ----------
__global__ __launch_bounds__(256, 3) void pass2_kernel(
    const int* __restrict__ Y, const float* __restrict__ mask,
    const float* __restrict__ logpi, const float* __restrict__ logA,
    const float* __restrict__ logB, float* __restrict__ out, int N, int NV)
{
    extern __shared__ uint2 tab2[];
    for (int i = threadIdx.x; i < NV; i += 256) tab2[i] = g_BtH[i];
    __syncthreads();

    const int tid = threadIdx.x;
    const int seq = blockIdx.x * 16 + (tid >> 4), k = tid & 15;
    W8 w = load_w(logA);

    float p0, p1, p2, p3, c, ap0, ap1, ap2, ap3;
    if (k == 0) {
        int y0 = __ldg(&Y[(size_t)seq * TT]);
        ap0 = __ldg(&logpi[0]) + __ldg(&logB[y0]);
        ap1 = __ldg(&logpi[1]) + __ldg(&logB[NV + y0]);
        ap2 = __ldg(&logpi[2]) + __ldg(&logB[2 * NV + y0]);
        ap3 = __ldg(&logpi[3]) + __ldg(&logB[3 * NV + y0]);
    } else {
        float4 a = __ldg(&g_S[k * N + seq]);
        ap0 = a.x; ap1 = a.y; ap2 = a.z; ap3 = a.w;
    }
    c  = fmaxf(fmaxf(ap0, ap1), fmaxf(ap2, ap3));
    p0 = exp2f((ap0 - c) * L2Ef); p1 = exp2f((ap1 - c) * L2Ef);
    p2 = exp2f((ap2 - c) * L2Ef); p3 = exp2f((ap3 - c) * L2Ef);

    const int4*   yp = (const int4*)(Y    + (size_t)seq * TT + 32 * k);
    const float4* mp = (const float4*)(mask + (size_t)seq * TT + 32 * k);
    float* rowp = out + (size_t)seq * (4 * TT) + k * 32;   // state-0 row, chunk origin

    int4   y4n = __ldg(yp);
    float4 m4n = __ldg(mp);
    int li = 1;

#pragma unroll 1
    for (int g = 0; g < 4; g++) {
        float4 an[8];
#pragma unroll
        for (int h = 0; h < 2; h++) {
            int4   y4 = y4n;
            float4 m4 = m4n;
            if (li < 8) { y4n = __ldg(yp + li); m4n = __ldg(mp + li); li++; }
            uint2 evs[4];
            evs[0] = tab2[y4.x]; evs[1] = tab2[y4.y];
            evs[2] = tab2[y4.z]; evs[3] = tab2[y4.w];
            float ma[4] = {m4.x, m4.y, m4.z, m4.w};
#pragma unroll
            for (int q = 0; q < 4; q++) {
                int j = h * 4 + q;
                if (k == 0 && g == 0 && j == 0) {
                    an[0] = make_float4(ap0, ap1, ap2, ap3);   // t=0: exact logs
                } else {
                    float e0, e1, e2, e3; unp(evs[q], e0, e1, e2, e3);
                    float qB = e0 * fmaf(w.ASB, p3, w.AEB * p2);
                    float qM = e1 * fmaf(w.AMM, p1, w.ABM * p0);
                    float qE = e2 * fmaf(w.AME, p1, w.ABE * p0);
                    float qS = e3 * fmaf(w.ASS, p3, w.AES * p2);
                    float n0 = fmaf(__log2f(qB), LN2f, c);
                    float n1 = fmaf(__log2f(qM), LN2f, c);
                    float n2 = fmaf(__log2f(qE), LN2f, c);
                    float n3 = fmaf(__log2f(qS), LN2f, c);
                    if (ma[q] == 1.0f) {
                        p0 = qB; p1 = qM; p2 = qE; p3 = qS;
                        if (q == 3) {
                            float mx = fmaxf(fmaxf(p0, p1), fmaxf(p2, p3));
                            int eb = __float_as_int(mx) >> 23;
                            float sc = __int_as_float((254 - eb) << 23);
                            c = fmaf((float)(eb - 127), LN2f, c);
                            p0 *= sc; p1 *= sc; p2 *= sc; p3 *= sc;
                        }
                    } else {
                        n0 = fmaf(ma[q], n0 - ap0, ap0);
                        n1 = fmaf(ma[q], n1 - ap1, ap1);
                        n2 = fmaf(ma[q], n2 - ap2, ap2);
                        n3 = fmaf(ma[q], n3 - ap3, ap3);
                        c  = fmaxf(fmaxf(n0, n1), fmaxf(n2, n3));
                        p0 = exp2f((n0 - c) * L2Ef); p1 = exp2f((n1 - c) * L2Ef);
                        p2 = exp2f((n2 - c) * L2Ef); p3 = exp2f((n3 - c) * L2Ef);
                    }
                    ap0 = n0; ap1 = n1; ap2 = n2; ap3 = n3;
                    an[j] = make_float4(n0, n1, n2, n3);
                }
            }
        }
        // direct stores: per state a full 32B sector (two aligned STG.128)
        float* gp = rowp + g * 8;
        *(float4*)(gp)               = make_float4(an[0].x, an[1].x, an[2].x, an[3].x);
        *(float4*)(gp + 4)           = make_float4(an[4].x, an[5].x, an[6].x, an[7].x);
        *(float4*)(gp + TT)          = make_float4(an[0].y, an[1].y, an[2].y, an[3].y);
        *(float4*)(gp + TT + 4)      = make_float4(an[4].y, an[5].y, an[6].y, an[7].y);
        *(float4*)(gp + 2 * TT)      = make_float4(an[0].z, an[1].z, an[2].z, an[3].z);
        *(float4*)(gp + 2 * TT + 4)  = make_float4(an[4].z, an[5].z, an[6].z, an[7].z);
        *(float4*)(gp + 3 * TT)      = make_float4(an[0].w, an[1].w, an[2].w, an[3].w);
        *(float4*)(gp + 3 * TT + 4)  = make_float4(an[4].w, an[5].w, an[6].w, an[7].w);
    }
}

extern "C" void kernel_launch(void* const* d_in, const int* in_sizes, int n_in,
                              void* d_out, int out_size) {
    const int*   Y     = (const int*)  d_in[0];
    const float* mask  = (const float*)d_in[1];
    const float* logpi = (const float*)d_in[2];
    const float* logA  = (const float*)d_in[3];
    const float* logB  = (const float*)d_in[4];
    float*       out   = (float*)d_out;

    const int N  = in_sizes[0] / TT;
    const int NV = in_sizes[4] / 4;

    const int smem1 = NV * 8;   // 48000 B (table only)

    cudaFuncSetAttribute(pass1_kernel, cudaFuncAttributeMaxDynamicSharedMemorySize, smem1);
    cudaFuncSetAttribute(pass2_kernel, cudaFuncAttributeMaxDynamicSharedMemorySize, smem1);

    prep_kernel<<<(NV + 255) / 256, 256>>>(logB, NV);
    pass1_kernel<<<((KM + 1) * N + 255) / 256, 256, smem1>>>(Y, mask, logpi, logA, logB, N, NV);
    mid_kernel<<<(N + 127) / 128, 128>>>(N);
    pass2_kernel<<<N / 16, 256, smem1>>>(Y, mask, logpi, logA, logB, out, N, NV);
}